// round 1
// baseline (speedup 1.0000x reference)
#include <cuda_runtime.h>
#include <cstdint>

#define Bn    8
#define Nn    8192
#define Cn    91
#define CAPc  155648          // 8192 * 19 (max classes/proposal with p > 0.05)
#define NB    9216            // histogram bins over score float bits >> 12
#define BASE_BIN 251084       // bits(0.05f) >> 12
#define SEL_CAP 4096
#define TPB2  1024
#define CHUNKn 1024
#define DETS  100
#define CLIPV 4.135166556742356f   // log(1000/16)

// ------------------------------------------------------------------
// static device scratch (no allocations allowed)
// ------------------------------------------------------------------
__device__ unsigned long long g_keys[Bn][CAPc];
__device__ float4             g_box [Bn][CAPc];
__device__ int                g_cnt [Bn];
__device__ int                g_hist[Bn][NB];

__device__ __forceinline__ void stf(float* o, int i, float v, int n) {
    if (i < n) o[i] = v;
}

// ------------------------------------------------------------------
// K0: zero counters + histogram
// ------------------------------------------------------------------
__global__ void k_zero() {
    int i = blockIdx.x * blockDim.x + threadIdx.x;
    if (i < Bn) g_cnt[i] = 0;
    if (i < Bn * NB) ((int*)g_hist)[i] = 0;
}

// ------------------------------------------------------------------
// K1: softmax + decode + filter + compact (one warp per proposal)
// ------------------------------------------------------------------
__global__ __launch_bounds__(256) void k_cand(const float* __restrict__ logits,
                                              const float* __restrict__ reg,
                                              const float* __restrict__ props) {
    int g    = blockIdx.x * 8 + (threadIdx.x >> 5);   // proposal index 0..65535
    int lane = threadIdx.x & 31;
    int b = g >> 13;
    int n = g & (Nn - 1);

    const float* L = logits + (size_t)g * Cn;
    float l0 = L[lane];
    float l1 = (lane + 32 < Cn) ? L[lane + 32] : -1e30f;
    float l2 = (lane + 64 < Cn) ? L[lane + 64] : -1e30f;

    float mx = fmaxf(l0, fmaxf(l1, l2));
    #pragma unroll
    for (int o = 16; o; o >>= 1) mx = fmaxf(mx, __shfl_xor_sync(0xffffffffu, mx, o));

    float e0 = expf(l0 - mx);
    float e1 = (lane + 32 < Cn) ? expf(l1 - mx) : 0.0f;
    float e2 = (lane + 64 < Cn) ? expf(l2 - mx) : 0.0f;
    float s = e0 + e1 + e2;
    #pragma unroll
    for (int o = 16; o; o >>= 1) s += __shfl_xor_sync(0xffffffffu, s, o);

    // proposal geometry (redundant per lane, cheap)
    float4 p = reinterpret_cast<const float4*>(props)[g];
    float w  = p.z - p.x;
    float h  = p.w - p.y;
    float cx = p.x + 0.5f * w;
    float cy = p.y + 0.5f * h;

    const float4* Q = reinterpret_cast<const float4*>(reg + (size_t)g * (Cn * 4));

    #pragma unroll
    for (int k = 0; k < 3; k++) {
        int c = lane + 32 * k;
        float e = (k == 0) ? e0 : (k == 1) ? e1 : e2;
        float sc = __fdiv_rn(e, s);
        bool ok = (c >= 1) && (c < Cn) && (sc > 0.05f);

        float x1 = 0.f, y1 = 0.f, x2 = 0.f, y2 = 0.f;
        if (ok) {
            float4 q = Q[c];
            float dx = __fdiv_rn(q.x, 10.0f);
            float dy = __fdiv_rn(q.y, 10.0f);
            float dw = fminf(__fdiv_rn(q.z, 5.0f), CLIPV);
            float dh = fminf(__fdiv_rn(q.w, 5.0f), CLIPV);
            float pcx = dx * w + cx;
            float pcy = dy * h + cy;
            float pw  = expf(dw) * w;
            float ph  = expf(dh) * h;
            x1 = pcx - 0.5f * pw;
            y1 = pcy - 0.5f * ph;
            x2 = pcx + 0.5f * pw;
            y2 = pcy + 0.5f * ph;
            x1 = fminf(fmaxf(x1, 0.f), 800.f);
            y1 = fminf(fmaxf(y1, 0.f), 800.f);
            x2 = fminf(fmaxf(x2, 0.f), 800.f);
            y2 = fminf(fmaxf(y2, 0.f), 800.f);
            float ws = x2 - x1, hs = y2 - y1;
            ok = (ws >= 1.0f) && (hs >= 1.0f);
        }

        unsigned mask = __ballot_sync(0xffffffffu, ok);
        int cnt = __popc(mask);
        if (cnt) {
            int leader = __ffs(mask) - 1;
            int base = 0;
            if (lane == leader) base = atomicAdd(&g_cnt[b], cnt);
            base = __shfl_sync(0xffffffffu, base, leader);
            if (ok) {
                int pos = base + __popc(mask & ((1u << lane) - 1u));
                if (pos < CAPc) {
                    unsigned m = (unsigned)(n * 90 + (c - 1));
                    unsigned sb = __float_as_uint(sc);
                    g_keys[b][pos] = ((unsigned long long)sb << 32) | (0xFFFFFFFFu - m);
                    g_box[b][pos]  = make_float4(x1, y1, x2, y2);
                    int bin = (int)(sb >> 12) - BASE_BIN;
                    bin = max(0, min(bin, NB - 1));
                    atomicAdd(&g_hist[b][bin], 1);
                }
            }
        }
    }
}

// ------------------------------------------------------------------
// K2: per-image top-window selection + bitonic sort + greedy NMS
// ------------------------------------------------------------------
struct SM {
    float4 sbox[CHUNKn];
    float4 abox[DETS];
    unsigned long long skey[SEL_CAP];
    int    sval[SEL_CAP];
    int    sfx[NB];
    int    part[TPB2];
    int    albl[DETS];
    int    s_cnt, s_flag, s_acc;
};

__global__ __launch_bounds__(TPB2) void k_nms(float* __restrict__ out, int out_size) {
    extern __shared__ char smraw[];
    SM* sm = reinterpret_cast<SM*>(smraw);
    int b = blockIdx.x;
    int t = threadIdx.x;

    // ---- suffix sums of histogram: sfx[i] = #candidates with bin >= i ----
    const int PER = NB / TPB2;   // 9
    int lo = t * PER;
    int ls = 0;
    #pragma unroll
    for (int i = 0; i < PER; i++) ls += g_hist[b][lo + i];
    sm->part[t] = ls;
    __syncthreads();
    for (int off = 1; off < TPB2; off <<= 1) {
        int v = sm->part[t] + ((t + off < TPB2) ? sm->part[t + off] : 0);
        __syncthreads();
        sm->part[t] = v;
        __syncthreads();
    }
    int run = sm->part[t] - ls;     // exclusive suffix of this thread's chunk
    for (int i = PER - 1; i >= 0; i--) {
        run += g_hist[b][lo + i];
        sm->sfx[lo + i] = run;
    }
    if (t == 0) sm->s_acc = 0;
    __syncthreads();

    int Ktot = min(g_cnt[b], CAPc);
    int b_hi = NB;

    while (sm->s_acc < DETS) {
        int top = (b_hi < NB) ? sm->sfx[b_hi] : 0;
        if (b_hi == 0 || sm->sfx[0] - top == 0) break;   // nothing left

        // smallest b_lo with sfx[b_lo] - top <= SEL_CAP (monotone -> binary search)
        int sl = 0, sh = b_hi;
        while (sl < sh) {
            int mid = (sl + sh) >> 1;
            if (sm->sfx[mid] - top <= SEL_CAP) sh = mid; else sl = mid + 1;
        }
        int wlo = sl;
        if (wlo >= b_hi) wlo = b_hi - 1;   // single-bucket overflow clamp
        int whi = b_hi;
        b_hi = wlo;

        if (t == 0) sm->s_cnt = 0;
        __syncthreads();
        for (int i = t; i < Ktot; i += TPB2) {
            unsigned long long key = g_keys[b][i];
            int bin = (int)((unsigned)(key >> 32) >> 12) - BASE_BIN;
            bin = max(0, min(bin, NB - 1));
            if (bin >= wlo && bin < whi) {
                int pos = atomicAdd(&sm->s_cnt, 1);
                if (pos < SEL_CAP) { sm->skey[pos] = key; sm->sval[pos] = i; }
            }
        }
        __syncthreads();
        int nsel = min(sm->s_cnt, SEL_CAP);
        if (nsel == 0) continue;

        int P = 1;
        while (P < nsel) P <<= 1;
        for (int i = nsel + t; i < P; i += TPB2) { sm->skey[i] = 0ULL; sm->sval[i] = 0; }
        __syncthreads();

        // ---- bitonic sort descending by key ----
        for (int k = 2; k <= P; k <<= 1) {
            for (int j = k >> 1; j > 0; j >>= 1) {
                for (int i = t; i < P; i += TPB2) {
                    int ixj = i ^ j;
                    if (ixj > i) {
                        unsigned long long a = sm->skey[i], c2 = sm->skey[ixj];
                        bool desc = ((i & k) == 0);
                        if (desc ? (a < c2) : (a > c2)) {
                            sm->skey[i] = c2; sm->skey[ixj] = a;
                            int va = sm->sval[i]; sm->sval[i] = sm->sval[ixj]; sm->sval[ixj] = va;
                        }
                    }
                }
                __syncthreads();
            }
        }

        // ---- sequential greedy NMS scan over sorted candidates ----
        for (int base2 = 0; base2 < nsel; base2 += CHUNKn) {
            if (sm->s_acc >= DETS) break;
            int take = min(CHUNKn, nsel - base2);
            __syncthreads();
            for (int i = t; i < take; i += TPB2)
                sm->sbox[i] = g_box[b][sm->sval[base2 + i]];
            __syncthreads();

            for (int j = 0; j < take; j++) {
                if (sm->s_acc >= DETS) break;
                unsigned long long key = sm->skey[base2 + j];
                unsigned m = 0xFFFFFFFFu - (unsigned)key;
                int lbl = 1 + (int)(m % 90u);
                float4 bx = sm->sbox[j];
                float off = (float)lbl * 801.0f;   // (max(H,W)+1) * label, as reference

                if (t == 0) sm->s_flag = 0;
                __syncthreads();
                int acc = sm->s_acc;
                if (t < acc && sm->albl[t] == lbl) {
                    float4 ab = sm->abox[t];
                    // replicate reference: IoU computed on offset coordinates
                    float ax1 = ab.x + off, ay1 = ab.y + off, ax2 = ab.z + off, ay2 = ab.w + off;
                    float bx1 = bx.x + off, by1 = bx.y + off, bx2 = bx.z + off, by2 = bx.w + off;
                    float ltx = fmaxf(ax1, bx1), lty = fmaxf(ay1, by1);
                    float rbx = fminf(ax2, bx2), rby = fminf(ay2, by2);
                    float ww = fmaxf(rbx - ltx, 0.f), hh = fmaxf(rby - lty, 0.f);
                    float inter = ww * hh;
                    float a1 = (ax2 - ax1) * (ay2 - ay1);
                    float a2 = (bx2 - bx1) * (by2 - by1);
                    float iou = inter / (a1 + a2 - inter + 1e-9f);
                    if (iou > 0.5f) sm->s_flag = 1;
                }
                __syncthreads();
                if (sm->s_flag == 0) {
                    if (t == 0) {
                        int a = sm->s_acc;
                        sm->abox[a] = bx;
                        sm->albl[a] = lbl;
                        float sc = __uint_as_float((unsigned)(key >> 32));
                        stf(out, b * (DETS * 4) + a * 4 + 0, bx.x, out_size);
                        stf(out, b * (DETS * 4) + a * 4 + 1, bx.y, out_size);
                        stf(out, b * (DETS * 4) + a * 4 + 2, bx.z, out_size);
                        stf(out, b * (DETS * 4) + a * 4 + 3, bx.w, out_size);
                        stf(out, Bn * DETS * 4 + b * DETS + a, sc, out_size);
                        stf(out, Bn * DETS * 5 + b * DETS + a, (float)lbl, out_size);
                        stf(out, Bn * DETS * 6 + b * DETS + a, 1.0f, out_size);
                        sm->s_acc = a + 1;
                    }
                }
                __syncthreads();
            }
        }
    }

    // ---- zero-fill remaining detection slots ----
    __syncthreads();
    int accF = sm->s_acc;
    for (int a = accF + t; a < DETS; a += TPB2) {
        stf(out, b * (DETS * 4) + a * 4 + 0, 0.f, out_size);
        stf(out, b * (DETS * 4) + a * 4 + 1, 0.f, out_size);
        stf(out, b * (DETS * 4) + a * 4 + 2, 0.f, out_size);
        stf(out, b * (DETS * 4) + a * 4 + 3, 0.f, out_size);
        stf(out, Bn * DETS * 4 + b * DETS + a, 0.f, out_size);
        stf(out, Bn * DETS * 5 + b * DETS + a, 0.f, out_size);
        stf(out, Bn * DETS * 6 + b * DETS + a, 0.f, out_size);
    }
}

// ------------------------------------------------------------------
// launcher
// ------------------------------------------------------------------
extern "C" void kernel_launch(void* const* d_in, const int* in_sizes, int n_in,
                              void* d_out, int out_size) {
    const float* logits = nullptr;
    const float* reg    = nullptr;
    const float* props  = nullptr;
    for (int i = 0; i < n_in; i++) {
        if      (in_sizes[i] == Bn * Nn * Cn)     logits = (const float*)d_in[i];
        else if (in_sizes[i] == Bn * Nn * Cn * 4) reg    = (const float*)d_in[i];
        else if (in_sizes[i] == Bn * Nn * 4)      props  = (const float*)d_in[i];
    }
    if (!logits && n_in > 0) logits = (const float*)d_in[0];
    if (!reg    && n_in > 1) reg    = (const float*)d_in[1];
    if (!props  && n_in > 2) props  = (const float*)d_in[2];

    cudaFuncSetAttribute(k_nms, cudaFuncAttributeMaxDynamicSharedMemorySize,
                         (int)sizeof(SM));

    int ztot = Bn * NB;
    k_zero<<<(ztot + 255) / 256, 256>>>();
    k_cand<<<(Bn * Nn) / 8, 256>>>(logits, reg, props);
    k_nms<<<Bn, TPB2, sizeof(SM)>>>((float*)d_out, out_size);
}

// round 2
// speedup vs baseline: 1.2892x; 1.2892x over previous
#include <cuda_runtime.h>
#include <cstdint>

#define Bn    8
#define Nn    8192
#define Cn    91
#define CAPc  155648          // 8192 * 19 (max classes/proposal with p > 0.05)
#define NB    9216            // histogram bins over score float bits >> 12
#define BASE_BIN 251084       // bits(0.05f) >> 12
#define SEL_CAP 1024
#define TPB2  1024
#define CHUNKn 1024
#define DETS  100
#define CLIPV 4.135166556742356f   // log(1000/16)

// ------------------------------------------------------------------
// static device scratch (no allocations allowed)
// ------------------------------------------------------------------
__device__ unsigned long long g_keys[Bn][CAPc];
__device__ float4             g_box [Bn][CAPc];
__device__ int                g_cnt [Bn];
__device__ int                g_hist[Bn][NB];

__device__ __forceinline__ void stf(float* o, int i, float v, int n) {
    if (i < n) o[i] = v;
}

// ------------------------------------------------------------------
// K0: zero counters + histogram
// ------------------------------------------------------------------
__global__ void k_zero() {
    int i = blockIdx.x * blockDim.x + threadIdx.x;
    if (i < Bn) g_cnt[i] = 0;
    if (i < Bn * NB) ((int*)g_hist)[i] = 0;
}

// ------------------------------------------------------------------
// K1: softmax + decode + filter + compact (one warp per proposal)
// ------------------------------------------------------------------
__global__ __launch_bounds__(256) void k_cand(const float* __restrict__ logits,
                                              const float* __restrict__ reg,
                                              const float* __restrict__ props) {
    int g    = blockIdx.x * 8 + (threadIdx.x >> 5);   // proposal index 0..65535
    int lane = threadIdx.x & 31;
    int b = g >> 13;
    int n = g & (Nn - 1);

    const float* L = logits + (size_t)g * Cn;
    float l0 = L[lane];
    float l1 = (lane + 32 < Cn) ? L[lane + 32] : -1e30f;
    float l2 = (lane + 64 < Cn) ? L[lane + 64] : -1e30f;

    float mx = fmaxf(l0, fmaxf(l1, l2));
    #pragma unroll
    for (int o = 16; o; o >>= 1) mx = fmaxf(mx, __shfl_xor_sync(0xffffffffu, mx, o));

    float e0 = expf(l0 - mx);
    float e1 = (lane + 32 < Cn) ? expf(l1 - mx) : 0.0f;
    float e2 = (lane + 64 < Cn) ? expf(l2 - mx) : 0.0f;
    float s = e0 + e1 + e2;
    #pragma unroll
    for (int o = 16; o; o >>= 1) s += __shfl_xor_sync(0xffffffffu, s, o);

    // proposal geometry (redundant per lane, cheap)
    float4 p = reinterpret_cast<const float4*>(props)[g];
    float w  = p.z - p.x;
    float h  = p.w - p.y;
    float cx = p.x + 0.5f * w;
    float cy = p.y + 0.5f * h;

    const float4* Q = reinterpret_cast<const float4*>(reg + (size_t)g * (Cn * 4));

    #pragma unroll
    for (int k = 0; k < 3; k++) {
        int c = lane + 32 * k;
        float e = (k == 0) ? e0 : (k == 1) ? e1 : e2;
        float sc = __fdiv_rn(e, s);
        bool ok = (c >= 1) && (c < Cn) && (sc > 0.05f);

        float x1 = 0.f, y1 = 0.f, x2 = 0.f, y2 = 0.f;
        if (ok) {
            float4 q = Q[c];
            float dx = __fdiv_rn(q.x, 10.0f);
            float dy = __fdiv_rn(q.y, 10.0f);
            float dw = fminf(__fdiv_rn(q.z, 5.0f), CLIPV);
            float dh = fminf(__fdiv_rn(q.w, 5.0f), CLIPV);
            float pcx = dx * w + cx;
            float pcy = dy * h + cy;
            float pw  = expf(dw) * w;
            float ph  = expf(dh) * h;
            x1 = pcx - 0.5f * pw;
            y1 = pcy - 0.5f * ph;
            x2 = pcx + 0.5f * pw;
            y2 = pcy + 0.5f * ph;
            x1 = fminf(fmaxf(x1, 0.f), 800.f);
            y1 = fminf(fmaxf(y1, 0.f), 800.f);
            x2 = fminf(fmaxf(x2, 0.f), 800.f);
            y2 = fminf(fmaxf(y2, 0.f), 800.f);
            float ws = x2 - x1, hs = y2 - y1;
            ok = (ws >= 1.0f) && (hs >= 1.0f);
        }

        unsigned mask = __ballot_sync(0xffffffffu, ok);
        int cnt = __popc(mask);
        if (cnt) {
            int leader = __ffs(mask) - 1;
            int base = 0;
            if (lane == leader) base = atomicAdd(&g_cnt[b], cnt);
            base = __shfl_sync(0xffffffffu, base, leader);
            if (ok) {
                int pos = base + __popc(mask & ((1u << lane) - 1u));
                if (pos < CAPc) {
                    unsigned m = (unsigned)(n * 90 + (c - 1));
                    unsigned sb = __float_as_uint(sc);
                    g_keys[b][pos] = ((unsigned long long)sb << 32) | (0xFFFFFFFFu - m);
                    g_box[b][pos]  = make_float4(x1, y1, x2, y2);
                    int bin = (int)(sb >> 12) - BASE_BIN;
                    bin = max(0, min(bin, NB - 1));
                    atomicAdd(&g_hist[b][bin], 1);
                }
            }
        }
    }
}

// ------------------------------------------------------------------
// K2: per-image top-window selection + bitonic sort + warp-level NMS
// ------------------------------------------------------------------
struct SM {
    float4 sbox[CHUNKn];
    unsigned long long skey[SEL_CAP];
    int    sval[SEL_CAP];
    int    sfx[NB];
    int    part[TPB2];
    int    s_cnt, s_acc;
};

__global__ __launch_bounds__(TPB2) void k_nms(float* __restrict__ out, int out_size) {
    extern __shared__ char smraw[];
    SM* sm = reinterpret_cast<SM*>(smraw);
    int b = blockIdx.x;
    int t = threadIdx.x;
    int lane = t & 31;

    // register-resident accepted state (warp 0 only, named to stay in regs)
    float4 ar0, ar1, ar2, ar3;
    int    al0 = -1, al1 = -1, al2 = -1, al3 = -1;
    ar0 = ar1 = ar2 = ar3 = make_float4(0.f, 0.f, 0.f, 0.f);

    // ---- suffix sums of histogram: sfx[i] = #candidates with bin >= i ----
    const int PER = NB / TPB2;   // 9
    int lo = t * PER;
    int ls = 0;
    #pragma unroll
    for (int i = 0; i < PER; i++) ls += g_hist[b][lo + i];
    sm->part[t] = ls;
    __syncthreads();
    for (int off = 1; off < TPB2; off <<= 1) {
        int v = sm->part[t] + ((t + off < TPB2) ? sm->part[t + off] : 0);
        __syncthreads();
        sm->part[t] = v;
        __syncthreads();
    }
    int run = sm->part[t] - ls;     // exclusive suffix of this thread's chunk
    for (int i = PER - 1; i >= 0; i--) {
        run += g_hist[b][lo + i];
        sm->sfx[lo + i] = run;
    }
    if (t == 0) sm->s_acc = 0;
    __syncthreads();

    int Ktot = min(g_cnt[b], CAPc);
    int b_hi = NB;

    while (sm->s_acc < DETS) {
        int top = (b_hi < NB) ? sm->sfx[b_hi] : 0;
        if (b_hi == 0 || sm->sfx[0] - top == 0) break;   // nothing left

        // smallest b_lo with sfx[b_lo] - top <= SEL_CAP (monotone -> binary search)
        int sl = 0, sh = b_hi;
        while (sl < sh) {
            int mid = (sl + sh) >> 1;
            if (sm->sfx[mid] - top <= SEL_CAP) sh = mid; else sl = mid + 1;
        }
        int wlo = sl;
        if (wlo >= b_hi) wlo = b_hi - 1;   // single-bucket overflow clamp
        int whi = b_hi;
        b_hi = wlo;

        if (t == 0) sm->s_cnt = 0;
        __syncthreads();
        for (int i = t; i < Ktot; i += TPB2) {
            unsigned long long key = g_keys[b][i];
            int bin = (int)((unsigned)(key >> 32) >> 12) - BASE_BIN;
            bin = max(0, min(bin, NB - 1));
            if (bin >= wlo && bin < whi) {
                int pos = atomicAdd(&sm->s_cnt, 1);
                if (pos < SEL_CAP) { sm->skey[pos] = key; sm->sval[pos] = i; }
            }
        }
        __syncthreads();
        int nsel = min(sm->s_cnt, SEL_CAP);
        if (nsel == 0) continue;

        int P = 1;
        while (P < nsel) P <<= 1;
        for (int i = nsel + t; i < P; i += TPB2) { sm->skey[i] = 0ULL; sm->sval[i] = 0; }
        __syncthreads();

        // ---- bitonic sort descending by key ----
        for (int k = 2; k <= P; k <<= 1) {
            for (int j = k >> 1; j > 0; j >>= 1) {
                for (int i = t; i < P; i += TPB2) {
                    int ixj = i ^ j;
                    if (ixj > i) {
                        unsigned long long a = sm->skey[i], c2 = sm->skey[ixj];
                        bool desc = ((i & k) == 0);
                        if (desc ? (a < c2) : (a > c2)) {
                            sm->skey[i] = c2; sm->skey[ixj] = a;
                            int va = sm->sval[i]; sm->sval[i] = sm->sval[ixj]; sm->sval[ixj] = va;
                        }
                    }
                }
                __syncthreads();
            }
        }

        // ---- greedy NMS: block prefetches boxes, warp 0 scans with
        //      register-resident accepted list, zero block barriers per j ----
        for (int base2 = 0; base2 < nsel; base2 += CHUNKn) {
            __syncthreads();
            if (sm->s_acc >= DETS) break;        // uniform
            int take = min(CHUNKn, nsel - base2);
            for (int i = t; i < take; i += TPB2)
                sm->sbox[i] = g_box[b][sm->sval[base2 + i]];
            __syncthreads();

            if (t < 32) {
                int acc = sm->s_acc;
                for (int j = 0; j < take && acc < DETS; j++) {
                    unsigned long long key = sm->skey[base2 + j];
                    float4 bx = sm->sbox[j];
                    unsigned m = 0xFFFFFFFFu - (unsigned)key;
                    int lbl = 1 + (int)(m % 90u);
                    float off = (float)lbl * 801.0f;   // (max(H,W)+1) * label
                    float bx1 = bx.x + off, by1 = bx.y + off;
                    float bx2 = bx.z + off, by2 = bx.w + off;
                    float a2 = (bx2 - bx1) * (by2 - by1);

                    bool sup = false;
                    #define IOU_SLOT(S, AR, AL)                                          \
                    {                                                                    \
                        int idx = (S) * 32 + lane;                                       \
                        if (idx < acc && (AL) == lbl) {                                  \
                            float ax1 = (AR).x + off, ay1 = (AR).y + off;                \
                            float ax2 = (AR).z + off, ay2 = (AR).w + off;                \
                            float ltx = fmaxf(ax1, bx1), lty = fmaxf(ay1, by1);          \
                            float rbx = fminf(ax2, bx2), rby = fminf(ay2, by2);          \
                            float ww = fmaxf(rbx - ltx, 0.f), hh = fmaxf(rby - lty, 0.f);\
                            float inter = ww * hh;                                       \
                            float a1 = (ax2 - ax1) * (ay2 - ay1);                        \
                            float iou = __fdiv_rn(inter, a1 + a2 - inter + 1e-9f);       \
                            sup |= (iou > 0.5f);                                         \
                        }                                                                \
                    }
                    IOU_SLOT(0, ar0, al0)
                    IOU_SLOT(1, ar1, al1)
                    IOU_SLOT(2, ar2, al2)
                    IOU_SLOT(3, ar3, al3)
                    #undef IOU_SLOT

                    if (__ballot_sync(0xffffffffu, sup) == 0u) {
                        if (lane == (acc & 31)) {
                            int ws2 = acc >> 5;
                            if      (ws2 == 0) { ar0 = bx; al0 = lbl; }
                            else if (ws2 == 1) { ar1 = bx; al1 = lbl; }
                            else if (ws2 == 2) { ar2 = bx; al2 = lbl; }
                            else               { ar3 = bx; al3 = lbl; }
                        }
                        if (lane == 0) {
                            float sc = __uint_as_float((unsigned)(key >> 32));
                            stf(out, b * (DETS * 4) + acc * 4 + 0, bx.x, out_size);
                            stf(out, b * (DETS * 4) + acc * 4 + 1, bx.y, out_size);
                            stf(out, b * (DETS * 4) + acc * 4 + 2, bx.z, out_size);
                            stf(out, b * (DETS * 4) + acc * 4 + 3, bx.w, out_size);
                            stf(out, Bn * DETS * 4 + b * DETS + acc, sc, out_size);
                            stf(out, Bn * DETS * 5 + b * DETS + acc, (float)lbl, out_size);
                            stf(out, Bn * DETS * 6 + b * DETS + acc, 1.0f, out_size);
                        }
                        acc++;
                    }
                }
                if (lane == 0) sm->s_acc = acc;
            }
            __syncthreads();
        }
        __syncthreads();
    }

    // ---- zero-fill remaining detection slots ----
    __syncthreads();
    int accF = sm->s_acc;
    for (int a = accF + t; a < DETS; a += TPB2) {
        stf(out, b * (DETS * 4) + a * 4 + 0, 0.f, out_size);
        stf(out, b * (DETS * 4) + a * 4 + 1, 0.f, out_size);
        stf(out, b * (DETS * 4) + a * 4 + 2, 0.f, out_size);
        stf(out, b * (DETS * 4) + a * 4 + 3, 0.f, out_size);
        stf(out, Bn * DETS * 4 + b * DETS + a, 0.f, out_size);
        stf(out, Bn * DETS * 5 + b * DETS + a, 0.f, out_size);
        stf(out, Bn * DETS * 6 + b * DETS + a, 0.f, out_size);
    }
}

// ------------------------------------------------------------------
// launcher
// ------------------------------------------------------------------
extern "C" void kernel_launch(void* const* d_in, const int* in_sizes, int n_in,
                              void* d_out, int out_size) {
    const float* logits = nullptr;
    const float* reg    = nullptr;
    const float* props  = nullptr;
    for (int i = 0; i < n_in; i++) {
        if      (in_sizes[i] == Bn * Nn * Cn)     logits = (const float*)d_in[i];
        else if (in_sizes[i] == Bn * Nn * Cn * 4) reg    = (const float*)d_in[i];
        else if (in_sizes[i] == Bn * Nn * 4)      props  = (const float*)d_in[i];
    }
    if (!logits && n_in > 0) logits = (const float*)d_in[0];
    if (!reg    && n_in > 1) reg    = (const float*)d_in[1];
    if (!props  && n_in > 2) props  = (const float*)d_in[2];

    cudaFuncSetAttribute(k_nms, cudaFuncAttributeMaxDynamicSharedMemorySize,
                         (int)sizeof(SM));

    int ztot = Bn * NB;
    k_zero<<<(ztot + 255) / 256, 256>>>();
    k_cand<<<(Bn * Nn) / 8, 256>>>(logits, reg, props);
    k_nms<<<Bn, TPB2, sizeof(SM)>>>((float*)d_out, out_size);
}

// round 3
// speedup vs baseline: 2.2039x; 1.7095x over previous
#include <cuda_runtime.h>
#include <cstdint>

#define Bn    8
#define Nn    8192
#define Cn    91
#define CAPc  163840          // 8192 * 20 (>= max classes/proposal with p > 0.05)
#define NB    9216            // histogram bins over score float bits >> 12
#define BASE_BIN 251084       // bits(0.05f) >> 12
#define SEL_CAP 1024
#define TPB2  1024
#define TILE  256
#define DETS  100
#define CLIPV 4.135166556742356f   // log(1000/16)
#define FULLM 0xffffffffu

// ------------------------------------------------------------------
// static device scratch (no allocations allowed; zero-initialized at load,
// k_nms restores the zeros it consumed -> graph-replay deterministic)
// ------------------------------------------------------------------
__device__ unsigned long long g_keys[Bn][CAPc];
__device__ float4             g_box [Bn][CAPc];
__device__ int                g_cnt [Bn];
__device__ int                g_hist[Bn][NB];

__device__ __forceinline__ void stf(float* o, int i, float v, int n) {
    if (i < n) o[i] = v;
}

// reference-rounding IoU on offset coordinates; returns (iou > 0.5)
__device__ __forceinline__ bool iou_sup(float4 A, float4 Bx, float off) {
    float ax1 = A.x + off, ay1 = A.y + off, ax2 = A.z + off, ay2 = A.w + off;
    float bx1 = Bx.x + off, by1 = Bx.y + off, bx2 = Bx.z + off, by2 = Bx.w + off;
    float ltx = fmaxf(ax1, bx1), lty = fmaxf(ay1, by1);
    float rbx = fminf(ax2, bx2), rby = fminf(ay2, by2);
    float ww = fmaxf(rbx - ltx, 0.f), hh = fmaxf(rby - lty, 0.f);
    float inter = ww * hh;
    float a1 = (ax2 - ax1) * (ay2 - ay1);
    float a2 = (bx2 - bx1) * (by2 - by1);
    float iou = __fdiv_rn(inter, a1 + a2 - inter + 1e-9f);
    return iou > 0.5f;
}

// ------------------------------------------------------------------
// K1: softmax + decode + filter + compact (one warp per proposal)
// ------------------------------------------------------------------
__global__ __launch_bounds__(256) void k_cand(const float* __restrict__ logits,
                                              const float* __restrict__ reg,
                                              const float* __restrict__ props) {
    int g    = blockIdx.x * 8 + (threadIdx.x >> 5);   // proposal index 0..65535
    int lane = threadIdx.x & 31;
    int b = g >> 13;
    int n = g & (Nn - 1);

    const float* L = logits + (size_t)g * Cn;
    float l0 = L[lane];
    float l1 = (lane + 32 < Cn) ? L[lane + 32] : -1e30f;
    float l2 = (lane + 64 < Cn) ? L[lane + 64] : -1e30f;

    float mx = fmaxf(l0, fmaxf(l1, l2));
    #pragma unroll
    for (int o = 16; o; o >>= 1) mx = fmaxf(mx, __shfl_xor_sync(FULLM, mx, o));

    float e0 = expf(l0 - mx);
    float e1 = (lane + 32 < Cn) ? expf(l1 - mx) : 0.0f;
    float e2 = (lane + 64 < Cn) ? expf(l2 - mx) : 0.0f;
    float s = e0 + e1 + e2;
    #pragma unroll
    for (int o = 16; o; o >>= 1) s += __shfl_xor_sync(FULLM, s, o);

    float4 p = reinterpret_cast<const float4*>(props)[g];
    float w  = p.z - p.x;
    float h  = p.w - p.y;
    float cx = p.x + 0.5f * w;
    float cy = p.y + 0.5f * h;

    const float4* Q = reinterpret_cast<const float4*>(reg + (size_t)g * (Cn * 4));

    bool  okv[3];
    float scv[3];
    float4 bxv[3];
    float pre_t = 0.0497f * s;   // conservative prefilter (>> 1ulp margin)

    #pragma unroll
    for (int k = 0; k < 3; k++) {
        int c = lane + 32 * k;
        float e = (k == 0) ? e0 : (k == 1) ? e1 : e2;
        bool ok = (c >= 1) && (c < Cn) && (e > pre_t);
        float sc = 0.f;
        float4 bx = make_float4(0.f, 0.f, 0.f, 0.f);
        if (ok) {
            sc = __fdiv_rn(e, s);          // exact softmax value
            ok = (sc > 0.05f);
            if (ok) {
                float4 q = Q[c];
                float dx = __fdiv_rn(q.x, 10.0f);
                float dy = __fdiv_rn(q.y, 10.0f);
                float dw = fminf(__fdiv_rn(q.z, 5.0f), CLIPV);
                float dh = fminf(__fdiv_rn(q.w, 5.0f), CLIPV);
                float pcx = dx * w + cx;
                float pcy = dy * h + cy;
                float pw  = expf(dw) * w;
                float ph  = expf(dh) * h;
                float x1 = fminf(fmaxf(pcx - 0.5f * pw, 0.f), 800.f);
                float y1 = fminf(fmaxf(pcy - 0.5f * ph, 0.f), 800.f);
                float x2 = fminf(fmaxf(pcx + 0.5f * pw, 0.f), 800.f);
                float y2 = fminf(fmaxf(pcy + 0.5f * ph, 0.f), 800.f);
                ok = ((x2 - x1) >= 1.0f) && ((y2 - y1) >= 1.0f);
                bx = make_float4(x1, y1, x2, y2);
            }
        }
        okv[k] = ok; scv[k] = sc; bxv[k] = bx;
    }

    unsigned mA = __ballot_sync(FULLM, okv[0]);
    unsigned mB = __ballot_sync(FULLM, okv[1]);
    unsigned mC = __ballot_sync(FULLM, okv[2]);
    int tot = __popc(mA) + __popc(mB) + __popc(mC);
    if (tot) {
        int base = 0;
        if (lane == 0) base = atomicAdd(&g_cnt[b], tot);
        base = __shfl_sync(FULLM, base, 0);
        unsigned below = (1u << lane) - 1u;
        int p0 = base + __popc(mA & below);
        int p1 = base + __popc(mA) + __popc(mB & below);
        int p2 = base + __popc(mA) + __popc(mB) + __popc(mC & below);

        #pragma unroll
        for (int k = 0; k < 3; k++) {
            if (okv[k]) {
                int pos = (k == 0) ? p0 : (k == 1) ? p1 : p2;
                if (pos < CAPc) {
                    int c = lane + 32 * k;
                    unsigned m = (unsigned)(n * 90 + (c - 1));
                    unsigned sb = __float_as_uint(scv[k]);
                    g_keys[b][pos] = ((unsigned long long)sb << 32) | (0xFFFFFFFFu - m);
                    g_box[b][pos]  = bxv[k];
                    int bin = (int)(sb >> 12) - BASE_BIN;
                    bin = max(0, min(bin, NB - 1));
                    atomicAdd(&g_hist[b][bin], 1);
                }
            }
        }
    }
}

// ------------------------------------------------------------------
// K2: per-image top-window selection + bitonic sort + mask-matrix NMS
// ------------------------------------------------------------------
struct SM {
    float4 sbox[SEL_CAP];               // sorted boxes
    float4 abox[DETS];                  // accepted boxes
    unsigned long long skey[SEL_CAP];
    int    sval[SEL_CAP];
    int    slbl[SEL_CAP];
    int    sfx[NB];
    unsigned mask[TILE * 8];            // within-tile suppression bitmask
    unsigned supw[8];                   // suppressed-by-accepted bits
    int    wtot[32], wexc[32];
    int    albl[DETS];
    int    s_cnt, s_acc;
};

__global__ __launch_bounds__(TPB2) void k_nms(float* __restrict__ out, int out_size) {
    extern __shared__ char smraw[];
    SM* sm = reinterpret_cast<SM*>(smraw);
    int b = blockIdx.x;
    int t = threadIdx.x;
    int lane = t & 31;
    int warp = t >> 5;

    // ---- hierarchical suffix sums: sfx[i] = #candidates with bin >= i ----
    const int PER = NB / TPB2;   // 9
    int lo = t * PER;
    int ls = 0;
    #pragma unroll
    for (int i = 0; i < PER; i++) ls += g_hist[b][lo + i];
    int v = ls;
    #pragma unroll
    for (int off = 1; off < 32; off <<= 1) {
        int u = __shfl_down_sync(FULLM, v, off);
        if (lane + off < 32) v += u;
    }
    if (lane == 0) sm->wtot[warp] = v;   // warp suffix total (= sum of warp)
    __syncthreads();
    if (t < 32) {
        int x = sm->wtot[t];
        int vv = x;
        #pragma unroll
        for (int off = 1; off < 32; off <<= 1) {
            int u = __shfl_down_sync(FULLM, vv, off);
            if (t + off < 32) vv += u;
        }
        sm->wexc[t] = vv - x;            // suffix excluding own warp
    }
    if (t == 0) sm->s_acc = 0;
    __syncthreads();
    int run = sm->wexc[warp] + (v - ls); // exclusive suffix for this thread
    for (int i = PER - 1; i >= 0; i--) {
        run += g_hist[b][lo + i];
        sm->sfx[lo + i] = run;
    }
    __syncthreads();

    int Ktot = min(g_cnt[b], CAPc);
    int b_hi = NB;

    while (sm->s_acc < DETS) {
        int top = (b_hi < NB) ? sm->sfx[b_hi] : 0;
        if (b_hi == 0 || sm->sfx[0] - top == 0) break;   // nothing left

        // smallest b_lo with sfx[b_lo] - top <= SEL_CAP
        int sl = 0, sh = b_hi;
        while (sl < sh) {
            int mid = (sl + sh) >> 1;
            if (sm->sfx[mid] - top <= SEL_CAP) sh = mid; else sl = mid + 1;
        }
        int wlo = sl;
        if (wlo >= b_hi) wlo = b_hi - 1;
        int whi = b_hi;
        b_hi = wlo;

        if (t == 0) sm->s_cnt = 0;
        __syncthreads();
        for (int i = t; i < Ktot; i += TPB2) {
            unsigned long long key = g_keys[b][i];
            int bin = (int)((unsigned)(key >> 32) >> 12) - BASE_BIN;
            bin = max(0, min(bin, NB - 1));
            if (bin >= wlo && bin < whi) {
                int pos = atomicAdd(&sm->s_cnt, 1);
                if (pos < SEL_CAP) { sm->skey[pos] = key; sm->sval[pos] = i; }
            }
        }
        __syncthreads();
        int nsel = min(sm->s_cnt, SEL_CAP);
        if (nsel == 0) continue;

        int P = 1;
        while (P < nsel) P <<= 1;
        for (int i = nsel + t; i < P; i += TPB2) { sm->skey[i] = 0ULL; sm->sval[i] = 0; }
        __syncthreads();

        // ---- bitonic sort descending by key ----
        for (int k = 2; k <= P; k <<= 1) {
            for (int j = k >> 1; j > 0; j >>= 1) {
                for (int i = t; i < P; i += TPB2) {
                    int ixj = i ^ j;
                    if (ixj > i) {
                        unsigned long long a = sm->skey[i], c2 = sm->skey[ixj];
                        bool desc = ((i & k) == 0);
                        if (desc ? (a < c2) : (a > c2)) {
                            sm->skey[i] = c2; sm->skey[ixj] = a;
                            int va = sm->sval[i]; sm->sval[i] = sm->sval[ixj]; sm->sval[ixj] = va;
                        }
                    }
                }
                __syncthreads();
            }
        }

        // ---- gather boxes + labels in sorted order ----
        for (int i = t; i < nsel; i += TPB2) {
            sm->sbox[i] = g_box[b][sm->sval[i]];
            unsigned m = 0xFFFFFFFFu - (unsigned)sm->skey[i];
            sm->slbl[i] = 1 + (int)(m % 90u);
        }
        __syncthreads();

        // ---- tiled mask-matrix NMS ----
        for (int j0 = 0; j0 < nsel; j0 += TILE) {
            int takeN = min(TILE, nsel - j0);
            if (t < 8) sm->supw[t] = 0;
            __syncthreads();
            int acc0 = sm->s_acc;

            // phase A: suppression by already-accepted boxes
            {
                int i = t & (TILE - 1);
                int q = t >> 8;                  // 0..3
                bool sup = false;
                if (i < takeN) {
                    float4 bi = sm->sbox[j0 + i];
                    int li = sm->slbl[j0 + i];
                    float off = (float)li * 801.0f;
                    for (int a = q; a < acc0; a += 4) {
                        if (sm->albl[a] == li && iou_sup(sm->abox[a], bi, off))
                            { sup = true; break; }
                    }
                }
                if (sup) atomicOr(&sm->supw[i >> 5], 1u << (i & 31));
            }

            // phase B: within-tile suppression mask (owner-exclusive words)
            for (int idx = t; idx < TILE * 8; idx += TPB2) {
                int i = idx >> 3, w2 = idx & 7;
                unsigned bits = 0;
                if (i < takeN && (w2 * 32 + 31) > i) {
                    float4 bi = sm->sbox[j0 + i];
                    int li = sm->slbl[j0 + i];
                    float off = (float)li * 801.0f;
                    int jb = max(w2 * 32, i + 1);
                    int je = min(takeN, w2 * 32 + 32);
                    for (int j = jb; j < je; j++) {
                        if (sm->slbl[j0 + j] == li &&
                            iou_sup(bi, sm->sbox[j0 + j], off))
                            bits |= 1u << (j - w2 * 32);
                    }
                }
                sm->mask[i * 8 + w2] = bits;
            }
            __syncthreads();

            // phase C: warp 0 word-walk (greedy accept in sorted order)
            if (t < 32) {
                int acc = acc0;
                unsigned remv = (lane < 8) ? sm->supw[lane] : 0u;
                for (int basew = 0; basew < takeN && acc < DETS; basew += 32) {
                    int wi = basew >> 5;
                    unsigned word = __shfl_sync(FULLM, remv, wi);
                    unsigned lim = (takeN - basew >= 32) ? FULLM
                                   : ((1u << (takeN - basew)) - 1u);
                    unsigned alive = ~word & lim;
                    while (alive && acc < DETS) {
                        int pbit = __ffs(alive) - 1;
                        int i = basew + pbit;
                        unsigned mrow = (lane < 8) ? sm->mask[i * 8 + lane] : 0u;
                        remv |= mrow;
                        if (lane == 0) {
                            float4 bx = sm->sbox[j0 + i];
                            int lbl = sm->slbl[j0 + i];
                            sm->abox[acc] = bx;
                            sm->albl[acc] = lbl;
                            float sc = __uint_as_float((unsigned)(sm->skey[j0 + i] >> 32));
                            stf(out, b * (DETS * 4) + acc * 4 + 0, bx.x, out_size);
                            stf(out, b * (DETS * 4) + acc * 4 + 1, bx.y, out_size);
                            stf(out, b * (DETS * 4) + acc * 4 + 2, bx.z, out_size);
                            stf(out, b * (DETS * 4) + acc * 4 + 3, bx.w, out_size);
                            stf(out, Bn * DETS * 4 + b * DETS + acc, sc, out_size);
                            stf(out, Bn * DETS * 5 + b * DETS + acc, (float)lbl, out_size);
                            stf(out, Bn * DETS * 6 + b * DETS + acc, 1.0f, out_size);
                        }
                        acc++;
                        unsigned nw = __shfl_sync(FULLM, remv, wi);
                        alive &= ~nw;
                        alive &= ~(1u << pbit);
                    }
                }
                if (lane == 0) sm->s_acc = acc;
            }
            __syncthreads();
            if (sm->s_acc >= DETS) break;
        }
        __syncthreads();
    }

    // ---- zero-fill remaining detection slots ----
    __syncthreads();
    int accF = sm->s_acc;
    for (int a = accF + t; a < DETS; a += TPB2) {
        stf(out, b * (DETS * 4) + a * 4 + 0, 0.f, out_size);
        stf(out, b * (DETS * 4) + a * 4 + 1, 0.f, out_size);
        stf(out, b * (DETS * 4) + a * 4 + 2, 0.f, out_size);
        stf(out, b * (DETS * 4) + a * 4 + 3, 0.f, out_size);
        stf(out, Bn * DETS * 4 + b * DETS + a, 0.f, out_size);
        stf(out, Bn * DETS * 5 + b * DETS + a, 0.f, out_size);
        stf(out, Bn * DETS * 6 + b * DETS + a, 0.f, out_size);
    }

    // ---- restore zeros for next graph replay ----
    for (int i = t; i < NB; i += TPB2) g_hist[b][i] = 0;
    if (t == 0) g_cnt[b] = 0;
}

// ------------------------------------------------------------------
// launcher
// ------------------------------------------------------------------
extern "C" void kernel_launch(void* const* d_in, const int* in_sizes, int n_in,
                              void* d_out, int out_size) {
    const float* logits = nullptr;
    const float* reg    = nullptr;
    const float* props  = nullptr;
    for (int i = 0; i < n_in; i++) {
        if      (in_sizes[i] == Bn * Nn * Cn)     logits = (const float*)d_in[i];
        else if (in_sizes[i] == Bn * Nn * Cn * 4) reg    = (const float*)d_in[i];
        else if (in_sizes[i] == Bn * Nn * 4)      props  = (const float*)d_in[i];
    }
    if (!logits && n_in > 0) logits = (const float*)d_in[0];
    if (!reg    && n_in > 1) reg    = (const float*)d_in[1];
    if (!props  && n_in > 2) props  = (const float*)d_in[2];

    cudaFuncSetAttribute(k_nms, cudaFuncAttributeMaxDynamicSharedMemorySize,
                         (int)sizeof(SM));

    k_cand<<<(Bn * Nn) / 8, 256>>>(logits, reg, props);
    k_nms<<<Bn, TPB2, sizeof(SM)>>>((float*)d_out, out_size);
}

// round 4
// speedup vs baseline: 2.2195x; 1.0071x over previous
#include <cuda_runtime.h>
#include <cstdint>

#define Bn    8
#define Nn    8192
#define Cn    91
#define Mx    (Nn*(Cn-1))     // 737280 flat candidate ids per image
#define CAPc  163840          // >= max kept candidates per image
#define NB    9216            // histogram bins over score float bits >> 12
#define BASE_BIN 251084       // bits(0.05f) >> 12
#define SEL_CAP 1024
#define TPB   1024
#define TILE  256
#define DETS  100
#define CLIPV 4.135166556742356f   // log(1000/16)
#define FULLM 0xffffffffu
#define CAND_BLOCKS 2048
#define BLK_PER_IMG 256            // cand blocks per image

// ------------------------------------------------------------------
// static device scratch (zero-initialized at load; the NMS blocks restore
// every zero they consume -> graph-replay deterministic)
// ------------------------------------------------------------------
__device__ unsigned long long g_keys[Bn][CAPc];
__device__ float4             g_box [Bn][Mx];
__device__ int                g_cnt [Bn];
__device__ int                g_hist[Bn][NB];
__device__ int                g_done[Bn];

__device__ __forceinline__ void stf(float* o, int i, float v, int n) {
    if (i < n) o[i] = v;
}

// reference-rounding IoU on offset coordinates; returns (iou > 0.5)
__device__ __forceinline__ bool iou_sup(float4 A, float4 Bx, float off) {
    float ax1 = A.x + off, ay1 = A.y + off, ax2 = A.z + off, ay2 = A.w + off;
    float bx1 = Bx.x + off, by1 = Bx.y + off, bx2 = Bx.z + off, by2 = Bx.w + off;
    float ltx = fmaxf(ax1, bx1), lty = fmaxf(ay1, by1);
    float rbx = fminf(ax2, bx2), rby = fminf(ay2, by2);
    float ww = fmaxf(rbx - ltx, 0.f), hh = fmaxf(rby - lty, 0.f);
    float inter = ww * hh;
    float a1 = (ax2 - ax1) * (ay2 - ay1);
    float a2 = (bx2 - bx1) * (by2 - by1);
    float iou = __fdiv_rn(inter, a1 + a2 - inter + 1e-9f);
    return iou > 0.5f;
}

// ------------------------------------------------------------------
// shared memory for the NMS role
// ------------------------------------------------------------------
struct SM {
    float4 sbox[SEL_CAP];               // sorted boxes        16384
    unsigned long long skey[SEL_CAP];   //                      8192
    int    slbl[SEL_CAP];               //                      4096
    int    sfx[NB];                     // suffix counts       36864
    unsigned mask[TILE * 8];            // within-tile bitmask  8192
    float4 abox[DETS];                  // accepted boxes       1600
    int    albl[DETS];                  //                       400
    unsigned supw[8];
    int    wtot[32], wexc[32];
    int    s_cnt, s_acc;
};

// ------------------------------------------------------------------
// candidate generation for one proposal (one warp)
// ------------------------------------------------------------------
__device__ __forceinline__ void cand_warp(int g, int lane,
                                          const float* __restrict__ logits,
                                          const float* __restrict__ reg,
                                          const float* __restrict__ props) {
    int b = g >> 13;
    int n = g & (Nn - 1);

    const float* L = logits + (size_t)g * Cn;
    float l0 = L[lane];
    float l1 = (lane + 32 < Cn) ? L[lane + 32] : -1e30f;
    float l2 = (lane + 64 < Cn) ? L[lane + 64] : -1e30f;

    float mx = fmaxf(l0, fmaxf(l1, l2));
    #pragma unroll
    for (int o = 16; o; o >>= 1) mx = fmaxf(mx, __shfl_xor_sync(FULLM, mx, o));

    float e0 = expf(l0 - mx);
    float e1 = (lane + 32 < Cn) ? expf(l1 - mx) : 0.0f;
    float e2 = (lane + 64 < Cn) ? expf(l2 - mx) : 0.0f;
    float s = e0 + e1 + e2;
    #pragma unroll
    for (int o = 16; o; o >>= 1) s += __shfl_xor_sync(FULLM, s, o);

    float4 p = reinterpret_cast<const float4*>(props)[g];
    float w  = p.z - p.x;
    float h  = p.w - p.y;
    float cx = p.x + 0.5f * w;
    float cy = p.y + 0.5f * h;

    const float4* Q = reinterpret_cast<const float4*>(reg + (size_t)g * (Cn * 4));

    bool  okv[3];
    float scv[3];
    float4 bxv[3];
    float pre_t = 0.0497f * s;   // conservative prefilter (>> 1ulp margin)

    #pragma unroll
    for (int k = 0; k < 3; k++) {
        int c = lane + 32 * k;
        float e = (k == 0) ? e0 : (k == 1) ? e1 : e2;
        bool ok = (c >= 1) && (c < Cn) && (e > pre_t);
        float sc = 0.f;
        float4 bx = make_float4(0.f, 0.f, 0.f, 0.f);
        if (ok) {
            sc = __fdiv_rn(e, s);          // exact softmax value
            ok = (sc > 0.05f);
            if (ok) {
                float4 q = Q[c];
                float dx = __fdiv_rn(q.x, 10.0f);
                float dy = __fdiv_rn(q.y, 10.0f);
                float dw = fminf(__fdiv_rn(q.z, 5.0f), CLIPV);
                float dh = fminf(__fdiv_rn(q.w, 5.0f), CLIPV);
                float pcx = dx * w + cx;
                float pcy = dy * h + cy;
                float pw  = expf(dw) * w;
                float ph  = expf(dh) * h;
                float x1 = fminf(fmaxf(pcx - 0.5f * pw, 0.f), 800.f);
                float y1 = fminf(fmaxf(pcy - 0.5f * ph, 0.f), 800.f);
                float x2 = fminf(fmaxf(pcx + 0.5f * pw, 0.f), 800.f);
                float y2 = fminf(fmaxf(pcy + 0.5f * ph, 0.f), 800.f);
                ok = ((x2 - x1) >= 1.0f) && ((y2 - y1) >= 1.0f);
                bx = make_float4(x1, y1, x2, y2);
            }
        }
        okv[k] = ok; scv[k] = sc; bxv[k] = bx;
    }

    unsigned mA = __ballot_sync(FULLM, okv[0]);
    unsigned mB = __ballot_sync(FULLM, okv[1]);
    unsigned mC = __ballot_sync(FULLM, okv[2]);
    int tot = __popc(mA) + __popc(mB) + __popc(mC);
    if (tot) {
        int base = 0;
        if (lane == 0) base = atomicAdd(&g_cnt[b], tot);
        base = __shfl_sync(FULLM, base, 0);
        unsigned below = (1u << lane) - 1u;
        int p0 = base + __popc(mA & below);
        int p1 = base + __popc(mA) + __popc(mB & below);
        int p2 = base + __popc(mA) + __popc(mB) + __popc(mC & below);

        #pragma unroll
        for (int k = 0; k < 3; k++) {
            if (okv[k]) {
                int pos = (k == 0) ? p0 : (k == 1) ? p1 : p2;
                if (pos < CAPc) {
                    int c = lane + 32 * k;
                    unsigned m = (unsigned)(n * 90 + (c - 1));
                    unsigned sb = __float_as_uint(scv[k]);
                    g_keys[b][pos] = ((unsigned long long)sb << 32) | (0xFFFFFFFFu - m);
                    g_box[b][m]    = bxv[k];          // box indexed by flat id
                    int bin = (int)(sb >> 12) - BASE_BIN;
                    bin = max(0, min(bin, NB - 1));
                    atomicAdd(&g_hist[b][bin], 1);
                }
            }
        }
    }
}

// ------------------------------------------------------------------
// fused kernel: blocks [0, CAND_BLOCKS) produce, blocks [CAND_BLOCKS,
// CAND_BLOCKS+Bn) consume (NMS), synchronized by g_done spin.
// ------------------------------------------------------------------
__global__ __launch_bounds__(TPB) void k_fused(const float* __restrict__ logits,
                                               const float* __restrict__ reg,
                                               const float* __restrict__ props,
                                               float* __restrict__ out,
                                               int out_size) {
    extern __shared__ __align__(16) char smraw[];
    int t = threadIdx.x;
    int lane = t & 31;
    int warp = t >> 5;

    if (blockIdx.x < CAND_BLOCKS) {
        // ================= producer role =================
        int g = blockIdx.x * 32 + warp;           // one proposal per warp
        cand_warp(g, lane, logits, reg, props);
        __threadfence();
        __syncthreads();
        if (t == 0) atomicAdd(&g_done[blockIdx.x / BLK_PER_IMG], 1);
        return;
    }

    // ================= consumer (NMS) role =================
    SM* sm = reinterpret_cast<SM*>(smraw);
    int b = blockIdx.x - CAND_BLOCKS;

    if (t == 0) {
        volatile int* dp = &g_done[b];
        while (*dp < BLK_PER_IMG) { __nanosleep(256); }
    }
    __syncthreads();
    __threadfence();

    // ---- hierarchical suffix sums: sfx[i] = #candidates with bin >= i ----
    const int PER = NB / TPB;   // 9
    int lo = t * PER;
    int ls = 0;
    #pragma unroll
    for (int i = 0; i < PER; i++) ls += g_hist[b][lo + i];
    int v = ls;
    #pragma unroll
    for (int off = 1; off < 32; off <<= 1) {
        int u = __shfl_down_sync(FULLM, v, off);
        if (lane + off < 32) v += u;
    }
    if (lane == 0) sm->wtot[warp] = v;
    __syncthreads();
    if (t < 32) {
        int x = sm->wtot[t];
        int vv = x;
        #pragma unroll
        for (int off = 1; off < 32; off <<= 1) {
            int u = __shfl_down_sync(FULLM, vv, off);
            if (t + off < 32) vv += u;
        }
        sm->wexc[t] = vv - x;
    }
    if (t == 0) sm->s_acc = 0;
    __syncthreads();
    int run = sm->wexc[warp] + (v - ls);
    for (int i = PER - 1; i >= 0; i--) {
        run += g_hist[b][lo + i];
        sm->sfx[lo + i] = run;
    }
    __syncthreads();

    int Ktot = min(g_cnt[b], CAPc);
    int b_hi = NB;

    while (sm->s_acc < DETS) {
        int top = (b_hi < NB) ? sm->sfx[b_hi] : 0;
        if (b_hi == 0 || sm->sfx[0] - top == 0) break;

        // smallest b_lo with sfx[b_lo] - top <= SEL_CAP
        int sl = 0, sh = b_hi;
        while (sl < sh) {
            int mid = (sl + sh) >> 1;
            if (sm->sfx[mid] - top <= SEL_CAP) sh = mid; else sl = mid + 1;
        }
        int wlo = sl;
        if (wlo >= b_hi) wlo = b_hi - 1;
        int whi = b_hi;
        b_hi = wlo;

        if (t == 0) sm->s_cnt = 0;
        __syncthreads();
        for (int i = t; i < Ktot; i += TPB) {
            unsigned long long key = g_keys[b][i];
            int bin = (int)((unsigned)(key >> 32) >> 12) - BASE_BIN;
            bin = max(0, min(bin, NB - 1));
            if (bin >= wlo && bin < whi) {
                int pos = atomicAdd(&sm->s_cnt, 1);
                if (pos < SEL_CAP) sm->skey[pos] = key;
            }
        }
        __syncthreads();
        int nsel = min(sm->s_cnt, SEL_CAP);
        if (nsel == 0) continue;

        // pad to fixed P = SEL_CAP with 0-keys (sort to the tail)
        for (int i = nsel + t; i < SEL_CAP; i += TPB) sm->skey[i] = 0ULL;
        __syncthreads();

        // ---- register+shfl bitonic sort, descending, P=1024 ----
        {
            unsigned long long key = sm->skey[t];
            #pragma unroll
            for (int k2 = 2; k2 <= SEL_CAP; k2 <<= 1) {
                for (int j = k2 >> 1; j > 0; j >>= 1) {
                    unsigned long long partner;
                    if (j >= 32) {
                        __syncthreads();
                        sm->skey[t] = key;
                        __syncthreads();
                        partner = sm->skey[t ^ j];
                    } else {
                        partner = __shfl_xor_sync(FULLM, key, j);
                    }
                    bool desc    = ((t & k2) == 0);
                    bool lowerIx = ((t & j) == 0);
                    bool takeMax = (desc == lowerIx);
                    bool pG      = (partner > key);
                    if (takeMax == pG) key = partner;
                }
            }
            __syncthreads();
            sm->skey[t] = key;
            __syncthreads();
        }

        // ---- gather boxes + labels in sorted order ----
        for (int i = t; i < nsel; i += TPB) {
            unsigned m = 0xFFFFFFFFu - (unsigned)sm->skey[i];
            sm->sbox[i] = g_box[b][m];
            sm->slbl[i] = 1 + (int)(m % 90u);
        }
        __syncthreads();

        // ---- tiled mask-matrix NMS ----
        for (int j0 = 0; j0 < nsel; j0 += TILE) {
            int takeN = min(TILE, nsel - j0);
            if (t < 8) sm->supw[t] = 0;
            __syncthreads();
            int acc0 = sm->s_acc;

            // phase A: suppression by already-accepted boxes
            {
                int i = t & (TILE - 1);
                int q = t >> 8;                  // 0..3
                bool sup = false;
                if (i < takeN) {
                    float4 bi = sm->sbox[j0 + i];
                    int li = sm->slbl[j0 + i];
                    float off = (float)li * 801.0f;
                    for (int a = q; a < acc0; a += 4) {
                        if (sm->albl[a] == li && iou_sup(sm->abox[a], bi, off))
                            { sup = true; break; }
                    }
                }
                if (sup) atomicOr(&sm->supw[i >> 5], 1u << (i & 31));
            }

            // phase B: within-tile suppression mask (owner-exclusive words)
            for (int idx = t; idx < TILE * 8; idx += TPB) {
                int i = idx >> 3, w2 = idx & 7;
                unsigned bits = 0;
                if (i < takeN && (w2 * 32 + 31) > i) {
                    float4 bi = sm->sbox[j0 + i];
                    int li = sm->slbl[j0 + i];
                    float off = (float)li * 801.0f;
                    int jb = max(w2 * 32, i + 1);
                    int je = min(takeN, w2 * 32 + 32);
                    for (int j = jb; j < je; j++) {
                        if (sm->slbl[j0 + j] == li &&
                            iou_sup(bi, sm->sbox[j0 + j], off))
                            bits |= 1u << (j - w2 * 32);
                    }
                }
                sm->mask[i * 8 + w2] = bits;
            }
            __syncthreads();

            // phase C: warp 0 word-walk (greedy accept in sorted order)
            if (t < 32) {
                int acc = acc0;
                unsigned remv = (lane < 8) ? sm->supw[lane] : 0u;
                for (int basew = 0; basew < takeN && acc < DETS; basew += 32) {
                    int wi = basew >> 5;
                    unsigned word = __shfl_sync(FULLM, remv, wi);
                    unsigned lim = (takeN - basew >= 32) ? FULLM
                                   : ((1u << (takeN - basew)) - 1u);
                    unsigned alive = ~word & lim;
                    while (alive && acc < DETS) {
                        int pbit = __ffs(alive) - 1;
                        int i = basew + pbit;
                        unsigned mrow = (lane < 8) ? sm->mask[i * 8 + lane] : 0u;
                        remv |= mrow;
                        if (lane == 0) {
                            float4 bx = sm->sbox[j0 + i];
                            int lbl = sm->slbl[j0 + i];
                            sm->abox[acc] = bx;
                            sm->albl[acc] = lbl;
                            float sc = __uint_as_float((unsigned)(sm->skey[j0 + i] >> 32));
                            stf(out, b * (DETS * 4) + acc * 4 + 0, bx.x, out_size);
                            stf(out, b * (DETS * 4) + acc * 4 + 1, bx.y, out_size);
                            stf(out, b * (DETS * 4) + acc * 4 + 2, bx.z, out_size);
                            stf(out, b * (DETS * 4) + acc * 4 + 3, bx.w, out_size);
                            stf(out, Bn * DETS * 4 + b * DETS + acc, sc, out_size);
                            stf(out, Bn * DETS * 5 + b * DETS + acc, (float)lbl, out_size);
                            stf(out, Bn * DETS * 6 + b * DETS + acc, 1.0f, out_size);
                        }
                        acc++;
                        unsigned nw = __shfl_sync(FULLM, remv, wi);
                        alive &= ~nw;
                        alive &= ~(1u << pbit);
                    }
                }
                if (lane == 0) sm->s_acc = acc;
            }
            __syncthreads();
            if (sm->s_acc >= DETS) break;
        }
        __syncthreads();
    }

    // ---- zero-fill remaining detection slots ----
    __syncthreads();
    int accF = sm->s_acc;
    for (int a = accF + t; a < DETS; a += TPB) {
        stf(out, b * (DETS * 4) + a * 4 + 0, 0.f, out_size);
        stf(out, b * (DETS * 4) + a * 4 + 1, 0.f, out_size);
        stf(out, b * (DETS * 4) + a * 4 + 2, 0.f, out_size);
        stf(out, b * (DETS * 4) + a * 4 + 3, 0.f, out_size);
        stf(out, Bn * DETS * 4 + b * DETS + a, 0.f, out_size);
        stf(out, Bn * DETS * 5 + b * DETS + a, 0.f, out_size);
        stf(out, Bn * DETS * 6 + b * DETS + a, 0.f, out_size);
    }

    // ---- restore zeros for next graph replay ----
    for (int i = t; i < NB; i += TPB) g_hist[b][i] = 0;
    if (t == 0) { g_cnt[b] = 0; g_done[b] = 0; }
}

// ------------------------------------------------------------------
// launcher
// ------------------------------------------------------------------
extern "C" void kernel_launch(void* const* d_in, const int* in_sizes, int n_in,
                              void* d_out, int out_size) {
    const float* logits = nullptr;
    const float* reg    = nullptr;
    const float* props  = nullptr;
    for (int i = 0; i < n_in; i++) {
        if      (in_sizes[i] == Bn * Nn * Cn)     logits = (const float*)d_in[i];
        else if (in_sizes[i] == Bn * Nn * Cn * 4) reg    = (const float*)d_in[i];
        else if (in_sizes[i] == Bn * Nn * 4)      props  = (const float*)d_in[i];
    }
    if (!logits && n_in > 0) logits = (const float*)d_in[0];
    if (!reg    && n_in > 1) reg    = (const float*)d_in[1];
    if (!props  && n_in > 2) props  = (const float*)d_in[2];

    cudaFuncSetAttribute(k_fused, cudaFuncAttributeMaxDynamicSharedMemorySize,
                         (int)sizeof(SM));

    k_fused<<<CAND_BLOCKS + Bn, TPB, sizeof(SM)>>>(logits, reg, props,
                                                   (float*)d_out, out_size);
}

// round 5
// speedup vs baseline: 2.2430x; 1.0106x over previous
#include <cuda_runtime.h>
#include <cstdint>

#define Bn    8
#define Nn    8192
#define Cn    91
#define Mx    (Nn*(Cn-1))     // 737280 flat candidate ids per image
#define CAPc  163840          // >= max kept candidates per image
#define NB    9216            // histogram bins over score float bits >> 12
#define BASE_BIN 251084       // bits(0.05f) >> 12
#define SEL_CAP 1024
#define TPB   1024
#define TILE  256
#define DETS  100
#define CLIPV 4.135166556742356f   // log(1000/16)
#define FULLM 0xffffffffu
#define CAND_BLOCKS 2048
#define BLK_PER_IMG 256            // cand blocks per image

// ------------------------------------------------------------------
// static device scratch (zero-initialized at load; the NMS blocks restore
// every zero they consume -> graph-replay deterministic)
// ------------------------------------------------------------------
__device__ unsigned long long g_keys[Bn][CAPc];
__device__ float4             g_box [Bn][Mx];
__device__ int                g_cnt [Bn];
__device__ int                g_hist[Bn][NB];
__device__ int                g_done[Bn];

__device__ __forceinline__ void stf(float* o, int i, float v, int n) {
    if (i < n) o[i] = v;
}

// reference-rounding IoU on offset coordinates; returns (iou > 0.5)
__device__ __forceinline__ bool iou_sup(float4 A, float4 Bx, float off) {
    float ax1 = A.x + off, ay1 = A.y + off, ax2 = A.z + off, ay2 = A.w + off;
    float bx1 = Bx.x + off, by1 = Bx.y + off, bx2 = Bx.z + off, by2 = Bx.w + off;
    float ltx = fmaxf(ax1, bx1), lty = fmaxf(ay1, by1);
    float rbx = fminf(ax2, bx2), rby = fminf(ay2, by2);
    float ww = fmaxf(rbx - ltx, 0.f), hh = fmaxf(rby - lty, 0.f);
    float inter = ww * hh;
    float a1 = (ax2 - ax1) * (ay2 - ay1);
    float a2 = (bx2 - bx1) * (by2 - by1);
    float iou = __fdiv_rn(inter, a1 + a2 - inter + 1e-9f);
    return iou > 0.5f;
}

// ------------------------------------------------------------------
// shared memory for the NMS role
// ------------------------------------------------------------------
struct SM {
    float4 sbox[SEL_CAP];               // sorted boxes        16384
    unsigned long long skey[SEL_CAP];   //                      8192
    int    slbl[SEL_CAP];               //                      4096
    int    sfx[NB];                     // suffix counts       36864
    unsigned mask[TILE * 8];            // within-tile bitmask  8192
    float4 abox[DETS];                  // accepted boxes       1600
    int    albl[DETS];                  //                       400
    unsigned supw[8];
    int    wtot[32], wexc[32];
    int    s_cnt, s_acc;
};

// ------------------------------------------------------------------
// candidate generation for one proposal (one warp)
// ------------------------------------------------------------------
__device__ __forceinline__ void cand_warp(int g, int lane,
                                          const float* __restrict__ logits,
                                          const float* __restrict__ reg,
                                          const float* __restrict__ props) {
    int b = g >> 13;
    int n = g & (Nn - 1);

    const float* L = logits + (size_t)g * Cn;
    float l0 = L[lane];
    float l1 = (lane + 32 < Cn) ? L[lane + 32] : -1e30f;
    float l2 = (lane + 64 < Cn) ? L[lane + 64] : -1e30f;

    float mx = fmaxf(l0, fmaxf(l1, l2));
    #pragma unroll
    for (int o = 16; o; o >>= 1) mx = fmaxf(mx, __shfl_xor_sync(FULLM, mx, o));

    float e0 = expf(l0 - mx);
    float e1 = (lane + 32 < Cn) ? expf(l1 - mx) : 0.0f;
    float e2 = (lane + 64 < Cn) ? expf(l2 - mx) : 0.0f;
    float s = e0 + e1 + e2;
    #pragma unroll
    for (int o = 16; o; o >>= 1) s += __shfl_xor_sync(FULLM, s, o);

    float4 p = reinterpret_cast<const float4*>(props)[g];
    float w  = p.z - p.x;
    float h  = p.w - p.y;
    float cx = p.x + 0.5f * w;
    float cy = p.y + 0.5f * h;

    const float4* Q = reinterpret_cast<const float4*>(reg + (size_t)g * (Cn * 4));

    bool  okv[3];
    float scv[3];
    float4 bxv[3];
    float pre_t = 0.0497f * s;   // conservative prefilter (>> 1ulp margin)

    #pragma unroll
    for (int k = 0; k < 3; k++) {
        int c = lane + 32 * k;
        float e = (k == 0) ? e0 : (k == 1) ? e1 : e2;
        bool ok = (c >= 1) && (c < Cn) && (e > pre_t);
        float sc = 0.f;
        float4 bx = make_float4(0.f, 0.f, 0.f, 0.f);
        if (ok) {
            sc = __fdiv_rn(e, s);          // exact softmax value
            ok = (sc > 0.05f);
            if (ok) {
                float4 q = Q[c];
                float dx = __fdiv_rn(q.x, 10.0f);
                float dy = __fdiv_rn(q.y, 10.0f);
                float dw = fminf(__fdiv_rn(q.z, 5.0f), CLIPV);
                float dh = fminf(__fdiv_rn(q.w, 5.0f), CLIPV);
                float pcx = dx * w + cx;
                float pcy = dy * h + cy;
                float pw  = expf(dw) * w;
                float ph  = expf(dh) * h;
                float x1 = fminf(fmaxf(pcx - 0.5f * pw, 0.f), 800.f);
                float y1 = fminf(fmaxf(pcy - 0.5f * ph, 0.f), 800.f);
                float x2 = fminf(fmaxf(pcx + 0.5f * pw, 0.f), 800.f);
                float y2 = fminf(fmaxf(pcy + 0.5f * ph, 0.f), 800.f);
                ok = ((x2 - x1) >= 1.0f) && ((y2 - y1) >= 1.0f);
                bx = make_float4(x1, y1, x2, y2);
            }
        }
        okv[k] = ok; scv[k] = sc; bxv[k] = bx;
    }

    unsigned mA = __ballot_sync(FULLM, okv[0]);
    unsigned mB = __ballot_sync(FULLM, okv[1]);
    unsigned mC = __ballot_sync(FULLM, okv[2]);
    int tot = __popc(mA) + __popc(mB) + __popc(mC);
    if (tot) {
        int base = 0;
        if (lane == 0) base = atomicAdd(&g_cnt[b], tot);
        base = __shfl_sync(FULLM, base, 0);
        unsigned below = (1u << lane) - 1u;
        int p0 = base + __popc(mA & below);
        int p1 = base + __popc(mA) + __popc(mB & below);
        int p2 = base + __popc(mA) + __popc(mB) + __popc(mC & below);

        #pragma unroll
        for (int k = 0; k < 3; k++) {
            if (okv[k]) {
                int pos = (k == 0) ? p0 : (k == 1) ? p1 : p2;
                if (pos < CAPc) {
                    int c = lane + 32 * k;
                    unsigned m = (unsigned)(n * 90 + (c - 1));
                    unsigned sb = __float_as_uint(scv[k]);
                    g_keys[b][pos] = ((unsigned long long)sb << 32) | (0xFFFFFFFFu - m);
                    g_box[b][m]    = bxv[k];          // box indexed by flat id
                    int bin = (int)(sb >> 12) - BASE_BIN;
                    bin = max(0, min(bin, NB - 1));
                    atomicAdd(&g_hist[b][bin], 1);
                }
            }
        }
    }
}

// ------------------------------------------------------------------
// fused kernel: blocks [0, Bn) are NMS consumers (resident from wave 1,
// spin on g_done); blocks [Bn, Bn+CAND_BLOCKS) are producers.
// ------------------------------------------------------------------
__global__ __launch_bounds__(TPB) void k_fused(const float* __restrict__ logits,
                                               const float* __restrict__ reg,
                                               const float* __restrict__ props,
                                               float* __restrict__ out,
                                               int out_size) {
    extern __shared__ __align__(16) char smraw[];
    int t = threadIdx.x;
    int lane = t & 31;
    int warp = t >> 5;

    if (blockIdx.x >= Bn) {
        // ================= producer role =================
        int pb = blockIdx.x - Bn;
        int g = pb * 32 + warp;                   // one proposal per warp
        cand_warp(g, lane, logits, reg, props);
        __threadfence();
        __syncthreads();
        if (t == 0) atomicAdd(&g_done[pb / BLK_PER_IMG], 1);
        return;
    }

    // ================= consumer (NMS) role =================
    SM* sm = reinterpret_cast<SM*>(smraw);
    int b = blockIdx.x;

    if (t == 0) {
        volatile int* dp = &g_done[b];
        while (*dp < BLK_PER_IMG) { __nanosleep(128); }
    }
    __syncthreads();
    __threadfence();

    // ---- hierarchical suffix sums: sfx[i] = #candidates with bin >= i ----
    const int PER = NB / TPB;   // 9
    int lo = t * PER;
    int ls = 0;
    #pragma unroll
    for (int i = 0; i < PER; i++) ls += g_hist[b][lo + i];
    int v = ls;
    #pragma unroll
    for (int off = 1; off < 32; off <<= 1) {
        int u = __shfl_down_sync(FULLM, v, off);
        if (lane + off < 32) v += u;
    }
    if (lane == 0) sm->wtot[warp] = v;
    __syncthreads();
    if (t < 32) {
        int x = sm->wtot[t];
        int vv = x;
        #pragma unroll
        for (int off = 1; off < 32; off <<= 1) {
            int u = __shfl_down_sync(FULLM, vv, off);
            if (t + off < 32) vv += u;
        }
        sm->wexc[t] = vv - x;
    }
    if (t == 0) sm->s_acc = 0;
    __syncthreads();
    int run = sm->wexc[warp] + (v - ls);
    for (int i = PER - 1; i >= 0; i--) {
        run += g_hist[b][lo + i];
        sm->sfx[lo + i] = run;
    }
    __syncthreads();

    int Ktot = min(g_cnt[b], CAPc);
    int b_hi = NB;

    while (sm->s_acc < DETS) {
        int top = (b_hi < NB) ? sm->sfx[b_hi] : 0;
        if (b_hi == 0 || sm->sfx[0] - top == 0) break;

        // smallest b_lo with sfx[b_lo] - top <= SEL_CAP
        int sl = 0, sh = b_hi;
        while (sl < sh) {
            int mid = (sl + sh) >> 1;
            if (sm->sfx[mid] - top <= SEL_CAP) sh = mid; else sl = mid + 1;
        }
        int wlo = sl;
        if (wlo >= b_hi) wlo = b_hi - 1;
        int whi = b_hi;
        b_hi = wlo;

        if (t == 0) sm->s_cnt = 0;
        __syncthreads();
        for (int i = t; i < Ktot; i += TPB) {
            unsigned long long key = g_keys[b][i];
            int bin = (int)((unsigned)(key >> 32) >> 12) - BASE_BIN;
            bin = max(0, min(bin, NB - 1));
            if (bin >= wlo && bin < whi) {
                int pos = atomicAdd(&sm->s_cnt, 1);
                if (pos < SEL_CAP) sm->skey[pos] = key;
            }
        }
        __syncthreads();
        int nsel = min(sm->s_cnt, SEL_CAP);
        if (nsel == 0) continue;

        // pad to fixed P = SEL_CAP with 0-keys (sort to the tail)
        for (int i = nsel + t; i < SEL_CAP; i += TPB) sm->skey[i] = 0ULL;
        __syncthreads();

        // ---- register+shfl bitonic sort, descending, P=1024 ----
        {
            unsigned long long key = sm->skey[t];
            #pragma unroll
            for (int k2 = 2; k2 <= SEL_CAP; k2 <<= 1) {
                for (int j = k2 >> 1; j > 0; j >>= 1) {
                    unsigned long long partner;
                    if (j >= 32) {
                        __syncthreads();
                        sm->skey[t] = key;
                        __syncthreads();
                        partner = sm->skey[t ^ j];
                    } else {
                        partner = __shfl_xor_sync(FULLM, key, j);
                    }
                    bool desc    = ((t & k2) == 0);
                    bool lowerIx = ((t & j) == 0);
                    bool takeMax = (desc == lowerIx);
                    bool pG      = (partner > key);
                    if (takeMax == pG) key = partner;
                }
            }
            __syncthreads();
            sm->skey[t] = key;
            __syncthreads();
        }

        // ---- gather boxes + labels in sorted order ----
        for (int i = t; i < nsel; i += TPB) {
            unsigned m = 0xFFFFFFFFu - (unsigned)sm->skey[i];
            sm->sbox[i] = g_box[b][m];
            sm->slbl[i] = 1 + (int)(m % 90u);
        }
        __syncthreads();

        // ---- tiled mask-matrix NMS ----
        for (int j0 = 0; j0 < nsel; j0 += TILE) {
            int takeN = min(TILE, nsel - j0);
            if (t < 8) sm->supw[t] = 0;
            __syncthreads();
            int acc0 = sm->s_acc;

            // phase A: suppression by already-accepted boxes
            {
                int i = t & (TILE - 1);
                int q = t >> 8;                  // 0..3
                bool sup = false;
                if (i < takeN) {
                    float4 bi = sm->sbox[j0 + i];
                    int li = sm->slbl[j0 + i];
                    float off = (float)li * 801.0f;
                    for (int a = q; a < acc0; a += 4) {
                        if (sm->albl[a] == li && iou_sup(sm->abox[a], bi, off))
                            { sup = true; break; }
                    }
                }
                if (sup) atomicOr(&sm->supw[i >> 5], 1u << (i & 31));
            }

            // phase B: within-tile suppression mask (owner-exclusive words)
            for (int idx = t; idx < TILE * 8; idx += TPB) {
                int i = idx >> 3, w2 = idx & 7;
                unsigned bits = 0;
                if (i < takeN && (w2 * 32 + 31) > i) {
                    float4 bi = sm->sbox[j0 + i];
                    int li = sm->slbl[j0 + i];
                    float off = (float)li * 801.0f;
                    int jb = max(w2 * 32, i + 1);
                    int je = min(takeN, w2 * 32 + 32);
                    for (int j = jb; j < je; j++) {
                        if (sm->slbl[j0 + j] == li &&
                            iou_sup(bi, sm->sbox[j0 + j], off))
                            bits |= 1u << (j - w2 * 32);
                    }
                }
                sm->mask[i * 8 + w2] = bits;
            }
            __syncthreads();

            // phase C: warp 0 word-walk (greedy accept in sorted order)
            if (t < 32) {
                int acc = acc0;
                unsigned remv = (lane < 8) ? sm->supw[lane] : 0u;
                for (int basew = 0; basew < takeN && acc < DETS; basew += 32) {
                    int wi = basew >> 5;
                    unsigned word = __shfl_sync(FULLM, remv, wi);
                    unsigned lim = (takeN - basew >= 32) ? FULLM
                                   : ((1u << (takeN - basew)) - 1u);
                    unsigned alive = ~word & lim;
                    while (alive && acc < DETS) {
                        int pbit = __ffs(alive) - 1;
                        int i = basew + pbit;
                        unsigned mrow = (lane < 8) ? sm->mask[i * 8 + lane] : 0u;
                        remv |= mrow;
                        if (lane == 0) {
                            float4 bx = sm->sbox[j0 + i];
                            int lbl = sm->slbl[j0 + i];
                            sm->abox[acc] = bx;
                            sm->albl[acc] = lbl;
                            float sc = __uint_as_float((unsigned)(sm->skey[j0 + i] >> 32));
                            stf(out, b * (DETS * 4) + acc * 4 + 0, bx.x, out_size);
                            stf(out, b * (DETS * 4) + acc * 4 + 1, bx.y, out_size);
                            stf(out, b * (DETS * 4) + acc * 4 + 2, bx.z, out_size);
                            stf(out, b * (DETS * 4) + acc * 4 + 3, bx.w, out_size);
                            stf(out, Bn * DETS * 4 + b * DETS + acc, sc, out_size);
                            stf(out, Bn * DETS * 5 + b * DETS + acc, (float)lbl, out_size);
                            stf(out, Bn * DETS * 6 + b * DETS + acc, 1.0f, out_size);
                        }
                        acc++;
                        unsigned nw = __shfl_sync(FULLM, remv, wi);
                        alive &= ~nw;
                        alive &= ~(1u << pbit);
                    }
                }
                if (lane == 0) sm->s_acc = acc;
            }
            __syncthreads();
            if (sm->s_acc >= DETS) break;
        }
        __syncthreads();
    }

    // ---- zero-fill remaining detection slots ----
    __syncthreads();
    int accF = sm->s_acc;
    for (int a = accF + t; a < DETS; a += TPB) {
        stf(out, b * (DETS * 4) + a * 4 + 0, 0.f, out_size);
        stf(out, b * (DETS * 4) + a * 4 + 1, 0.f, out_size);
        stf(out, b * (DETS * 4) + a * 4 + 2, 0.f, out_size);
        stf(out, b * (DETS * 4) + a * 4 + 3, 0.f, out_size);
        stf(out, Bn * DETS * 4 + b * DETS + a, 0.f, out_size);
        stf(out, Bn * DETS * 5 + b * DETS + a, 0.f, out_size);
        stf(out, Bn * DETS * 6 + b * DETS + a, 0.f, out_size);
    }

    // ---- restore zeros for next graph replay ----
    for (int i = t; i < NB; i += TPB) g_hist[b][i] = 0;
    if (t == 0) { g_cnt[b] = 0; g_done[b] = 0; }
}

// ------------------------------------------------------------------
// launcher
// ------------------------------------------------------------------
extern "C" void kernel_launch(void* const* d_in, const int* in_sizes, int n_in,
                              void* d_out, int out_size) {
    const float* logits = nullptr;
    const float* reg    = nullptr;
    const float* props  = nullptr;
    for (int i = 0; i < n_in; i++) {
        if      (in_sizes[i] == Bn * Nn * Cn)     logits = (const float*)d_in[i];
        else if (in_sizes[i] == Bn * Nn * Cn * 4) reg    = (const float*)d_in[i];
        else if (in_sizes[i] == Bn * Nn * 4)      props  = (const float*)d_in[i];
    }
    if (!logits && n_in > 0) logits = (const float*)d_in[0];
    if (!reg    && n_in > 1) reg    = (const float*)d_in[1];
    if (!props  && n_in > 2) props  = (const float*)d_in[2];

    cudaFuncSetAttribute(k_fused, cudaFuncAttributeMaxDynamicSharedMemorySize,
                         (int)sizeof(SM));

    k_fused<<<Bn + CAND_BLOCKS, TPB, sizeof(SM)>>>(logits, reg, props,
                                                   (float*)d_out, out_size);
}